// round 17
// baseline (speedup 1.0000x reference)
#include <cuda_runtime.h>
#include <cuda_bf16.h>

// Problem constants
#define BB 8
#define SS 2048
#define FF 256
#define HH 8
#define DD 64
#define PROJ 512            // HH*DD
#define NSC 32              // s-chunks (64 rows each)
#define SCH 64              // rows per chunk

// Scratch (device globals — no allocation allowed)
__device__ float g_p[BB * HH * FF];             // p[b][h][f] = Wk_h @ q_last
__device__ float g_cm[BB * HH * NSC * 2];       // per-chunk (max, sumexp)
__device__ float g_yc[BB * NSC * HH * FF];      // unnormalized chunk sums (2MB)
__device__ float g_op[BB * 16 * FF];            // partial outputs per (h,fh)
__device__ unsigned int g_pcnt[BB];             // prep-done count; reset in k_proj
__device__ unsigned int g_pcnt2[BB];            // proj-done count; reset in k_flash

// =========================================================================
// K1 (k_flash): 256 blocks (b, chunk) x 256 threads, 2 blocks/SM guaranteed.
//   Prep sub-phase: block computes p[b, h=chunk>>2, f-quarter=chunk&3]
//                   (perfectly balanced: 32 blocks <-> 32 p-tiles per b).
//   Release g_pcnt[b]; spin until all 32 done; then flash body.
// =========================================================================
__global__ __launch_bounds__(256, 2)
void k_flash(const float* __restrict__ x,
             const float* __restrict__ Wq,
             const float* __restrict__ Wk) {
    int blk = blockIdx.x;
    int b = blk >> 5;
    int chunk = blk & 31;
    int t = threadIdx.x;
    int warp = t >> 5, lane = t & 31;

    // prep smem
    __shared__ float xs[FF];
    __shared__ float qred[4][DD];
    __shared__ float qs[DD];
    __shared__ float qp4[4][DD];
    // flash smem
    __shared__ float ps[HH * FF];       // 8KB
    __shared__ float sbuf[HH][SCH];     // 2KB
    __shared__ float ws[HH][SCH];       // 2KB
    __shared__ float mh[HH];
    __shared__ float4 redB[HH][64];     // 8KB

    if (blk == 0 && t < BB) g_pcnt2[t] = 0u;   // replay-safe reset for k_proj

    // ---------------- prep: p[b, h_p, fq*64 .. fq*64+64) -------------------
    {
        int h_p = chunk >> 2;
        int fq = chunk & 3;

        if (t < FF) xs[t] = x[((size_t)b * SS + (SS - 1)) * FF + t];
        __syncthreads();

        {   // q_h[d]: 256 threads = 64 d x 4 f-parts of 64; batched loads
            int d = t & 63, part = t >> 6;
            const float* wq = Wq + (size_t)(part * 64) * PROJ + h_p * DD + d;
            const float* xf = xs + part * 64;
            float a = 0.f;
            #pragma unroll
            for (int g = 0; g < 4; ++g) {
                float w[16];
                #pragma unroll
                for (int i = 0; i < 16; ++i) w[i] = wq[(size_t)(g * 16 + i) * PROJ];
                #pragma unroll
                for (int i = 0; i < 16; ++i) a += xf[g * 16 + i] * w[i];
            }
            qred[part][d] = a;
        }
        __syncthreads();
        if (t < DD) qs[t] = qred[0][t] + qred[1][t] + qred[2][t] + qred[3][t];
        __syncthreads();

        {   // p-quarter: 256 threads = 64 f x 4 d-parts of 16
            int fl = t & 63, dp = t >> 6;
            int f = fq * 64 + fl;
            const float4* wk4 = (const float4*)(Wk + (size_t)f * PROJ + h_p * DD + dp * 16);
            const float4* q4 = (const float4*)(qs + dp * 16);
            float4 w0 = wk4[0], w1 = wk4[1], w2 = wk4[2], w3 = wk4[3];
            float4 q0 = q4[0], q1 = q4[1], q2 = q4[2], q3 = q4[3];
            float a = w0.x * q0.x + w0.y * q0.y + w0.z * q0.z + w0.w * q0.w
                    + w1.x * q1.x + w1.y * q1.y + w1.z * q1.z + w1.w * q1.w
                    + w2.x * q2.x + w2.y * q2.y + w2.z * q2.z + w2.w * q2.w
                    + w3.x * q3.x + w3.y * q3.y + w3.z * q3.z + w3.w * q3.w;
            qp4[dp][fl] = a;
        }
        __syncthreads();
        if (t < 64)
            g_p[(b * HH + h_p) * FF + fq * 64 + t]
                = qp4[0][t] + qp4[1][t] + qp4[2][t] + qp4[3][t];

        // release: make g_p stores visible, then count up
        __threadfence();
        __syncthreads();
        if (t == 0) atomicAdd(&g_pcnt[b], 1u);
    }

    // ---------------- wait for all 32 p-tiles of this b ---------------------
    if (t == 0) {
        while (((volatile unsigned int*)g_pcnt)[b] < 32u) { }
        __threadfence();
    }
    __syncthreads();

    // ---------------- flash over (b, chunk) --------------------------------
    for (int i = t; i < HH * FF; i += 256) ps[i] = g_p[b * HH * FF + i];
    __syncthreads();

    const float4* ps4 = (const float4*)ps;
    const float4* xr_base = (const float4*)(x + ((size_t)b * SS + chunk * SCH) * FF);

    // Phase A: scores
    #pragma unroll
    for (int it = 0; it < 2; ++it) {
        int r0 = it * 32 + warp * 4;
        const float4* xr = xr_base + (size_t)r0 * 64;

        float4 a[4], c[4];
        #pragma unroll
        for (int r = 0; r < 4; ++r) {
            a[r] = xr[r * 64 + lane];
            c[r] = xr[r * 64 + 32 + lane];
        }

        #pragma unroll
        for (int r = 0; r < 4; ++r) {
            float dot[HH];
            #pragma unroll
            for (int h = 0; h < HH; ++h) {
                float4 pa = ps4[h * 64 + lane];
                float4 pc = ps4[h * 64 + 32 + lane];
                dot[h] = a[r].x * pa.x + a[r].y * pa.y + a[r].z * pa.z + a[r].w * pa.w
                       + c[r].x * pc.x + c[r].y * pc.y + c[r].z * pc.z + c[r].w * pc.w;
            }
            #pragma unroll
            for (int h = 0; h < HH; ++h) {
                #pragma unroll
                for (int o = 16; o; o >>= 1)
                    dot[h] += __shfl_xor_sync(0xFFFFFFFFu, dot[h], o);
            }
            if (lane == 0) {
                #pragma unroll
                for (int h = 0; h < HH; ++h)
                    sbuf[h][r0 + r] = dot[h] * 0.125f;
            }
        }
    }
    __syncthreads();

    // local stats: warp h handles head h
    if (warp < HH) {
        int h = warp;
        float v0 = sbuf[h][lane], v1 = sbuf[h][lane + 32];
        float m = fmaxf(v0, v1);
        #pragma unroll
        for (int o = 16; o; o >>= 1) m = fmaxf(m, __shfl_xor_sync(0xFFFFFFFFu, m, o));
        float s = __expf(v0 - m) + __expf(v1 - m);
        #pragma unroll
        for (int o = 16; o; o >>= 1) s += __shfl_xor_sync(0xFFFFFFFFu, s, o);
        if (lane == 0) {
            int idx = ((b * HH + h) * NSC + chunk) * 2;
            g_cm[idx] = m;
            g_cm[idx + 1] = s;
            mh[h] = m;
        }
    }
    __syncthreads();

    // unnormalized weights
    #pragma unroll
    for (int i = 0; i < 2; ++i) {
        int e = t + i * 256;
        int h = e >> 6, s = e & 63;
        ws[h][s] = __expf(sbuf[h][s] - mh[h]);
    }
    __syncthreads();

    // Phase B: weighted sum; (sg = s-half, hg = head-quad, f4)
    {
        int f4 = t & 63;
        int hg = (t >> 6) & 1;
        int sg = t >> 7;
        int h0 = hg * 4;

        float4 acc[4];
        #pragma unroll
        for (int q = 0; q < 4; ++q) acc[q] = make_float4(0.f, 0.f, 0.f, 0.f);

        #pragma unroll 4
        for (int i = 0; i < 32; ++i) {
            int s = sg * 32 + i;
            float4 xv = xr_base[(size_t)s * 64 + f4];
            #pragma unroll
            for (int q = 0; q < 4; ++q) {
                float w = ws[h0 + q][s];
                acc[q].x += w * xv.x; acc[q].y += w * xv.y;
                acc[q].z += w * xv.z; acc[q].w += w * xv.w;
            }
        }

        if (sg == 1) {
            #pragma unroll
            for (int q = 0; q < 4; ++q) redB[h0 + q][f4] = acc[q];
        }
        __syncthreads();
        if (sg == 0) {
            float4* out4 = (float4*)(g_yc + ((size_t)(b * NSC + chunk)) * (HH * FF));
            #pragma unroll
            for (int q = 0; q < 4; ++q) {
                float4 o = redB[h0 + q][f4];
                acc[q].x += o.x; acc[q].y += o.y; acc[q].z += o.z; acc[q].w += o.w;
                out4[(h0 + q) * 64 + f4] = acc[q];
            }
        }
    }
}

// -------------------------------------------------------------------------
// K2 (k_proj): per (b,h,fh): y_half -> @Wv_half -> attn_s[64] -> @Wo -> g_op.
//     Last block per b (atomic count == 15) sums 16 partials + bias -> out.
//     Also resets g_pcnt for the next replay's k_flash.
// grid: BB*HH*2 = 128 blocks, 512 threads
// -------------------------------------------------------------------------
__global__ void k_proj(const float* __restrict__ Wv,
                       const float* __restrict__ Wo,
                       const float* __restrict__ bo,
                       float* __restrict__ out) {
    int blk = blockIdx.x;
    int b = blk >> 4;
    int h = (blk >> 1) & 7;
    int fh = blk & 1;
    int t = threadIdx.x;
    __shared__ float scales[NSC];
    __shared__ float stats[1];
    __shared__ float red[3][128];
    __shared__ float ys[128];
    __shared__ float ared[8][DD];
    __shared__ float attn_s[DD];
    __shared__ float4 red4[7][64];      // 7KB
    __shared__ int isLast;

    if (blk == 0 && t < BB) g_pcnt[t] = 0u;    // replay-safe reset for k_flash

    if (t < 32) {   // warp 0: global stats + per-chunk scales
        const float* cm = g_cm + (size_t)(b * HH + h) * NSC * 2;
        float m = cm[t * 2], d = cm[t * 2 + 1];
        float M = m;
        #pragma unroll
        for (int o = 16; o; o >>= 1) M = fmaxf(M, __shfl_xor_sync(0xFFFFFFFFu, M, o));
        float e = __expf(m - M);
        scales[t] = e;
        float ds = d * e;
        #pragma unroll
        for (int o = 16; o; o >>= 1) ds += __shfl_xor_sync(0xFFFFFFFFu, ds, o);
        if (t == 0) stats[0] = 1.f / ds;
    }
    __syncthreads();
    float invD = stats[0];

    {   // y-half: 512 threads = 128 f x 4 chunk-groups of 8; batched loads
        int f = t & 127, cg = t >> 7;
        const float* pp = g_yc + ((size_t)(b * NSC + cg * 8) * HH + h) * FF + fh * 128 + f;
        float v[8];
        #pragma unroll
        for (int c = 0; c < 8; ++c) v[c] = pp[(size_t)c * (HH * FF)];
        float s = 0.f;
        #pragma unroll
        for (int c = 0; c < 8; ++c) s += scales[cg * 8 + c] * v[c];
        if (cg > 0) red[cg - 1][f] = s;
        __syncthreads();
        if (cg == 0) ys[f] = (s + red[0][f] + red[1][f] + red[2][f]) * invD;
    }
    __syncthreads();

    {   // partial attn: 512 threads = 64 d x 8 f-parts of 16; batched loads
        int d = t & 63, part = t >> 6;
        const float* wv = Wv + (size_t)(fh * 128 + part * 16) * PROJ + h * DD + d;
        const float* yf = ys + part * 16;
        float w[16];
        #pragma unroll
        for (int f = 0; f < 16; ++f) w[f] = wv[(size_t)f * PROJ];
        float a = 0.f;
        #pragma unroll
        for (int f = 0; f < 16; ++f) a += yf[f] * w[f];
        ared[part][d] = a;
    }
    __syncthreads();
    if (t < DD) {
        float s = 0.f;
        #pragma unroll
        for (int p = 0; p < 8; ++p) s += ared[p][t];
        attn_s[t] = s;
    }
    __syncthreads();

    {   // Wo projection: 512 threads = 64 j4 x 8 d-parts of 8
        int j4 = t & 63, dp = t >> 6;
        const float4* wo4 = (const float4*)Wo + (size_t)(h * DD + dp * 8) * 64 + j4;
        const float* ad = attn_s + dp * 8;
        float4 w[8];
        #pragma unroll
        for (int i = 0; i < 8; ++i) w[i] = wo4[(size_t)i * 64];
        float4 acc = make_float4(0.f, 0.f, 0.f, 0.f);
        #pragma unroll
        for (int i = 0; i < 8; ++i) {
            float a = ad[i];
            acc.x += a * w[i].x; acc.y += a * w[i].y;
            acc.z += a * w[i].z; acc.w += a * w[i].w;
        }
        if (dp > 0) red4[dp - 1][j4] = acc;
        __syncthreads();
        if (dp == 0) {
            #pragma unroll
            for (int g = 0; g < 7; ++g) {
                float4 o = red4[g][j4];
                acc.x += o.x; acc.y += o.y; acc.z += o.z; acc.w += o.w;
            }
            float4* op = (float4*)g_op + (size_t)(b * 16 + h * 2 + fh) * 64 + j4;
            *op = acc;
        }
    }

    // last-block-per-b finalization (deterministic fixed-order sum)
    __threadfence();
    __syncthreads();
    if (t == 0) {
        isLast = (atomicAdd(&g_pcnt2[b], 1u) == 15u) ? 1 : 0;
    }
    __syncthreads();
    if (isLast && t < FF) {
        const float* pp = g_op + (size_t)b * 16 * FF + t;
        float v[16];
        #pragma unroll
        for (int p = 0; p < 16; ++p) v[p] = pp[(size_t)p * FF];
        float s = bo[t];
        #pragma unroll
        for (int p = 0; p < 16; ++p) s += v[p];
        out[(size_t)b * FF + t] = s;
    }
}

// -------------------------------------------------------------------------
extern "C" void kernel_launch(void* const* d_in, const int* in_sizes, int n_in,
                              void* d_out, int out_size) {
    const float* x  = (const float*)d_in[0];
    const float* Wq = (const float*)d_in[1];
    const float* Wk = (const float*)d_in[2];
    const float* Wv = (const float*)d_in[3];
    const float* Wo = (const float*)d_in[4];
    const float* bo = (const float*)d_in[5];
    float* out = (float*)d_out;

    k_flash<<<BB * NSC, 256>>>(x, Wq, Wk);
    k_proj<<<BB * HH * 2, 512>>>(Wv, Wo, bo, out);
}